// round 9
// baseline (speedup 1.0000x reference)
#include <cuda_runtime.h>
#include <cuda_fp16.h>

#define Dd 48
#define Hh 256
#define Ww 256
#define DMk 48
#define HMk 128
#define WMk 128
#define PHn 4
#define CS (Dd * Hh * Ww * 2)          // 6,291,456 floats per phase slab
#define NPIX (Dd * Hh * Ww)            // 3,145,728 pixels
#define MVF_CH (DMk * HMk * WMk)       // 786,432 floats per mvf channel

// 25 MB fp16 x-pair scratch: g_pair[i][0] = half2(img[i].c0,   img[i].c1)
//                            g_pair[i][1] = half2(img[i+1].c0, img[i+1].c1)
// (x+1 clamped within the row). One aligned 8B load = both channels, both x-taps.
__device__ __align__(8) __half2 g_pair[NPIX][2];

// ---------------------------------------------------------------------------
// Prep: build fp16 pair scratch AND write passthrough slab out[:,0] = image.
// ---------------------------------------------------------------------------
__global__ void __launch_bounds__(256)
prep_kernel(const float2* __restrict__ img2, float2* __restrict__ out2) {
    int i = blockIdx.x * blockDim.x + threadIdx.x;
    if (i >= NPIX) return;
    int x = i & (Ww - 1);
    float2 a = __ldg(img2 + i);
    float2 b = __ldg(img2 + i + (x < Ww - 1 ? 1 : 0));
    g_pair[i][0] = __floats2half2_rn(a.x, a.y);
    g_pair[i][1] = __floats2half2_rn(b.x, b.y);
    out2[i] = a;
}

__device__ __forceinline__ __half2 h2_of(unsigned u) {
    __half2 h;
    *reinterpret_cast<unsigned*>(&h) = u;
    return h;
}
__device__ __forceinline__ __half2 h2lerp(__half2 a, __half2 b, __half2 w) {
    return __hfma2(w, __hsub2(b, a), a);   // a + w*(b-a)
}

// ---------------------------------------------------------------------------
// Trilinear grid-sample via fp16 pair scratch.
// Fast path (warp-uniformly interior): one base address + 3 immediate-offset
// LDG.64, full half2 lerp tree (x,y,z), single final convert.
// Slow path (boundary warps): exact fp32 weight-product form with per-axis
// validity zeroing + clamped indices (zeros padding semantics).
// ---------------------------------------------------------------------------
__device__ __forceinline__ float2 sample3d_h(float cz, float cy, float cx) {
    bool interior = (cz >= 0.f) & (cz < (float)(Dd - 1)) &
                    (cy >= 0.f) & (cy < (float)(Hh - 1)) &
                    (cx >= 0.f) & (cx < (float)(Ww - 1));

    if (__all_sync(0xffffffffu, interior)) {
        int z0 = (int)cz, y0 = (int)cy, x0 = (int)cx;   // nonneg: trunc==floor
        __half2 wz = __float2half2_rn(cz - (float)z0);
        __half2 wy = __float2half2_rn(cy - (float)y0);
        __half2 wx = __float2half2_rn(cx - (float)x0);

        const uint2* q = reinterpret_cast<const uint2*>(g_pair)
                         + ((z0 * Hh + y0) * Ww + x0);
        uint2 r00 = __ldg(q);                 // (z0, y0)
        uint2 r01 = __ldg(q + Ww);            // (z0, y1)
        uint2 r10 = __ldg(q + Hh * Ww);       // (z1, y0)
        uint2 r11 = __ldg(q + Hh * Ww + Ww);  // (z1, y1)

        __half2 x00 = h2lerp(h2_of(r00.x), h2_of(r00.y), wx);
        __half2 x01 = h2lerp(h2_of(r01.x), h2_of(r01.y), wx);
        __half2 x10 = h2lerp(h2_of(r10.x), h2_of(r10.y), wx);
        __half2 x11 = h2lerp(h2_of(r11.x), h2_of(r11.y), wx);
        __half2 y0v = h2lerp(x00, x01, wy);
        __half2 y1v = h2lerp(x10, x11, wy);
        __half2 zv  = h2lerp(y0v, y1v, wz);
        return __half22float2(zv);
    }

    // --- boundary path (rare, warp-uniform) ---
    float zf = floorf(cz), yf = floorf(cy), xf = floorf(cx);
    float fz = cz - zf, fy = cy - yf, fx = cx - xf;
    int z0 = (int)zf, y0 = (int)yf, x0 = (int)xf;
    int z1 = z0 + 1, y1 = y0 + 1;

    float wzv[2], wyv[2];
    wzv[0] = (1.f - fz) * (((unsigned)z0 < (unsigned)Dd) ? 1.f : 0.f);
    wzv[1] = fz         * (((unsigned)z1 < (unsigned)Dd) ? 1.f : 0.f);
    wyv[0] = (1.f - fy) * (((unsigned)y0 < (unsigned)Hh) ? 1.f : 0.f);
    wyv[1] = fy         * (((unsigned)y1 < (unsigned)Hh) ? 1.f : 0.f);
    float wx0 = (1.f - fx) * (((unsigned)x0       < (unsigned)Ww) ? 1.f : 0.f);
    float wx1 = fx         * (((unsigned)(x0 + 1) < (unsigned)Ww) ? 1.f : 0.f);

    int zi[2] = {min(max(z0, 0), Dd - 1), min(max(z1, 0), Dd - 1)};
    int yi[2] = {min(max(y0, 0), Hh - 1), min(max(y1, 0), Hh - 1)};
    int xc0   = min(max(x0, 0), Ww - 1);
    bool hiOK = (x0 >= 0);   // x0 == -1: both x-taps resolve to img[0]

    float ax = 0.f, ay = 0.f;
#pragma unroll
    for (int a = 0; a < 2; a++) {
#pragma unroll
        for (int b = 0; b < 2; b++) {
            float wzy = wzv[a] * wyv[b];
            uint2 raw = __ldg(reinterpret_cast<const uint2*>(
                                  g_pair[(zi[a] * Hh + yi[b]) * Ww + xc0]));
            float2 lo = __half22float2(h2_of(raw.x));
            float2 hi = __half22float2(h2_of(raw.y));
            float c1x = hiOK ? hi.x : lo.x;
            float c1y = hiOK ? hi.y : lo.y;
            ax = fmaf(wzy, fmaf(wx0, lo.x, wx1 * c1x), ax);
            ay = fmaf(wzy, fmaf(wx0, lo.y, wx1 * c1y), ay);
        }
    }
    return make_float2(ax, ay);
}

// ---------------------------------------------------------------------------
// Fused: on-the-fly 2x linear upsample of mvf (H,W dims; D identity; jax
// half-pixel convention, edge-clamp == JAX renormalization), flow scale
// (1,2,2), grid-sample, channel-last float2 store.
// Block = 256 threads = one output x-row; grid = (Hh, Dd, PHn).
// ---------------------------------------------------------------------------
__global__ void __launch_bounds__(256)
warp_kernel(const float* __restrict__ mvf, float* __restrict__ out) {
    __shared__ float ymix[3][WMk];

    int tx = threadIdx.x;      // 0..255 = output x
    int y  = blockIdx.x;       // 0..255
    int z  = blockIdx.y;       // 0..47
    int ph = blockIdx.z;       // 0..3

    // y-dim resize taps (uniform across block):
    // out[2k] = .25*in[k-1] + .75*in[k]; out[2k+1] = .75*in[k] + .25*in[k+1]
    int  yk   = y >> 1;
    bool yodd = (y & 1) != 0;
    int  ya   = yodd ? yk : (yk > 0 ? yk - 1 : 0);
    int  yb   = yodd ? (yk < HMk - 1 ? yk + 1 : HMk - 1) : yk;
    float wya = yodd ? 0.75f : 0.25f;
    float wyb = 1.f - wya;

    const float* mbase = mvf + (size_t)ph * 3 * MVF_CH + (size_t)z * HMk * WMk;
    if (tx < WMk) {
#pragma unroll
        for (int c = 0; c < 3; c++) {
            const float* rowa = mbase + (size_t)c * MVF_CH + ya * WMk;
            const float* rowb = mbase + (size_t)c * MVF_CH + yb * WMk;
            ymix[c][tx] = fmaf(wya, __ldg(rowa + tx), wyb * __ldg(rowb + tx));
        }
    }
    __syncthreads();

    // x-dim resize taps for this output x = tx
    int  k    = tx >> 1;
    bool xodd = (tx & 1) != 0;
    int  xa   = xodd ? k : (k > 0 ? k - 1 : 0);
    int  xb   = xodd ? (k < WMk - 1 ? k + 1 : WMk - 1) : k;
    float wxa = xodd ? 0.75f : 0.25f;
    float wxb = 1.f - wxa;

    float v[3];
#pragma unroll
    for (int c = 0; c < 3; c++)
        v[c] = fmaf(wxa, ymix[c][xa], wxb * ymix[c][xb]);

    // flow scale (1, 2, 2); coords are absolute voxel coordinates
    float2 r = sample3d_h((float)z + v[0],
                          (float)y + 2.f * v[1],
                          (float)tx + 2.f * v[2]);

    float2* o2 = (float2*)(out + (size_t)(1 + ph) * CS);
    o2[(z * Hh + y) * Ww + tx] = r;
}

// ---------------------------------------------------------------------------
extern "C" void kernel_launch(void* const* d_in, const int* in_sizes, int n_in,
                              void* d_out, int out_size) {
    const float* image = (const float*)d_in[0];   // (1,1,48,256,256,2) f32
    const float* mvf   = (const float*)d_in[1];   // (1,4,3,48,128,128) f32
    float* out = (float*)d_out;                   // (1,5,48,256,256,2) f32

    prep_kernel<<<(NPIX + 255) / 256, 256>>>((const float2*)image,
                                             (float2*)out);

    dim3 grid(Hh, Dd, PHn);
    warp_kernel<<<grid, 256>>>(mvf, out);
}

// round 10
// speedup vs baseline: 1.1654x; 1.1654x over previous
#include <cuda_runtime.h>
#include <cuda_fp16.h>

#define Dd 48
#define Hh 256
#define Ww 256
#define DMk 48
#define HMk 128
#define WMk 128
#define PHn 4
#define CS (Dd * Hh * Ww * 2)          // 6,291,456 floats per phase slab
#define NPIX (Dd * Hh * Ww)            // 3,145,728 pixels
#define MVF_CH (DMk * HMk * WMk)       // 786,432 floats per mvf channel

// 25 MB fp16 x-pair scratch: g_pair[i][0] = half2(img[i].c0,   img[i].c1)
//                            g_pair[i][1] = half2(img[i+1].c0, img[i+1].c1)
// (x+1 clamped within the row). One aligned 8B load = both channels, both x-taps.
__device__ __align__(8) __half2 g_pair[NPIX][2];

// ---------------------------------------------------------------------------
// Prep: build fp16 pair scratch AND write passthrough slab out[:,0] = image.
// ---------------------------------------------------------------------------
__global__ void __launch_bounds__(256)
prep_kernel(const float2* __restrict__ img2, float2* __restrict__ out2) {
    int i = blockIdx.x * blockDim.x + threadIdx.x;
    if (i >= NPIX) return;
    int x = i & (Ww - 1);
    float2 a = __ldg(img2 + i);
    float2 b = __ldg(img2 + i + (x < Ww - 1 ? 1 : 0));
    g_pair[i][0] = __floats2half2_rn(a.x, a.y);
    g_pair[i][1] = __floats2half2_rn(b.x, b.y);
    out2[i] = a;
}

__device__ __forceinline__ __half2 h2_of(unsigned u) {
    __half2 h;
    *reinterpret_cast<unsigned*>(&h) = u;
    return h;
}
__device__ __forceinline__ __half2 h2lerp(__half2 a, __half2 b, __half2 w) {
    return __hfma2(w, __hsub2(b, a), a);   // a + w*(b-a)
}

__device__ __forceinline__ bool is_interior(float cz, float cy, float cx) {
    return (cz >= 0.f) & (cz < (float)(Dd - 1)) &
           (cy >= 0.f) & (cy < (float)(Hh - 1)) &
           (cx >= 0.f) & (cx < (float)(Ww - 1));
}

// Interior trilinear sample: loads returned for batching; lerp tree in half2.
__device__ __forceinline__ void fast_addrs(float cz, float cy, float cx,
                                           const uint2*& q,
                                           __half2& wz, __half2& wy, __half2& wx) {
    int z0 = (int)cz, y0 = (int)cy, x0 = (int)cx;   // nonneg: trunc==floor
    wz = __float2half2_rn(cz - (float)z0);
    wy = __float2half2_rn(cy - (float)y0);
    wx = __float2half2_rn(cx - (float)x0);
    q  = reinterpret_cast<const uint2*>(g_pair) + ((z0 * Hh + y0) * Ww + x0);
}

__device__ __forceinline__ float2 fast_lerp(uint2 r00, uint2 r01,
                                            uint2 r10, uint2 r11,
                                            __half2 wz, __half2 wy, __half2 wx) {
    __half2 x00 = h2lerp(h2_of(r00.x), h2_of(r00.y), wx);
    __half2 x01 = h2lerp(h2_of(r01.x), h2_of(r01.y), wx);
    __half2 x10 = h2lerp(h2_of(r10.x), h2_of(r10.y), wx);
    __half2 x11 = h2lerp(h2_of(r11.x), h2_of(r11.y), wx);
    __half2 y0v = h2lerp(x00, x01, wy);
    __half2 y1v = h2lerp(x10, x11, wy);
    return __half22float2(h2lerp(y0v, y1v, wz));
}

// ---------------------------------------------------------------------------
// Single-sample path with its own warp-uniform fast/slow split (used by
// boundary warps; identical math to the pair fast path when interior).
// ---------------------------------------------------------------------------
__device__ __forceinline__ float2 sample3d_h(float cz, float cy, float cx) {
    bool interior = is_interior(cz, cy, cx);
    if (__all_sync(0xffffffffu, interior)) {
        const uint2* q; __half2 wz, wy, wx;
        fast_addrs(cz, cy, cx, q, wz, wy, wx);
        uint2 r00 = __ldg(q);
        uint2 r01 = __ldg(q + Ww);
        uint2 r10 = __ldg(q + Hh * Ww);
        uint2 r11 = __ldg(q + Hh * Ww + Ww);
        return fast_lerp(r00, r01, r10, r11, wz, wy, wx);
    }

    // --- boundary path: exact fp32 weights, per-axis validity, clamped idx ---
    float zf = floorf(cz), yf = floorf(cy), xf = floorf(cx);
    float fz = cz - zf, fy = cy - yf, fx = cx - xf;
    int z0 = (int)zf, y0 = (int)yf, x0 = (int)xf;
    int z1 = z0 + 1, y1 = y0 + 1;

    float wzv[2], wyv[2];
    wzv[0] = (1.f - fz) * (((unsigned)z0 < (unsigned)Dd) ? 1.f : 0.f);
    wzv[1] = fz         * (((unsigned)z1 < (unsigned)Dd) ? 1.f : 0.f);
    wyv[0] = (1.f - fy) * (((unsigned)y0 < (unsigned)Hh) ? 1.f : 0.f);
    wyv[1] = fy         * (((unsigned)y1 < (unsigned)Hh) ? 1.f : 0.f);
    float wx0 = (1.f - fx) * (((unsigned)x0       < (unsigned)Ww) ? 1.f : 0.f);
    float wx1 = fx         * (((unsigned)(x0 + 1) < (unsigned)Ww) ? 1.f : 0.f);

    int zi[2] = {min(max(z0, 0), Dd - 1), min(max(z1, 0), Dd - 1)};
    int yi[2] = {min(max(y0, 0), Hh - 1), min(max(y1, 0), Hh - 1)};
    int xc0   = min(max(x0, 0), Ww - 1);
    bool hiOK = (x0 >= 0);   // x0 == -1: both x-taps resolve to img[0]

    float ax = 0.f, ay = 0.f;
#pragma unroll
    for (int a = 0; a < 2; a++) {
#pragma unroll
        for (int b = 0; b < 2; b++) {
            float wzy = wzv[a] * wyv[b];
            uint2 raw = __ldg(reinterpret_cast<const uint2*>(
                                  g_pair[(zi[a] * Hh + yi[b]) * Ww + xc0]));
            float2 lo = __half22float2(h2_of(raw.x));
            float2 hi = __half22float2(h2_of(raw.y));
            float c1x = hiOK ? hi.x : lo.x;
            float c1y = hiOK ? hi.y : lo.y;
            ax = fmaf(wzy, fmaf(wx0, lo.x, wx1 * c1x), ax);
            ay = fmaf(wzy, fmaf(wx0, lo.y, wx1 * c1y), ay);
        }
    }
    return make_float2(ax, ay);
}

// ---------------------------------------------------------------------------
// Fused warp kernel, y-pair per thread:
// block = 256 threads = one x-row; grid = (Hh/2, Dd, PHn). Thread computes
// output pixels (z, 2*gy, tx) and (z, 2*gy+1, tx). All 8 corner loads of the
// pair issue before any lerp (MLP=8); the two samples' corner rows overlap
// (~50%) giving L1 hits on the second sample.
// mvf staging: rows gy-1, gy, gy+1 serve BOTH output rows.
// ---------------------------------------------------------------------------
__global__ void __launch_bounds__(256)
warp_kernel(const float* __restrict__ mvf, float* __restrict__ out) {
    __shared__ float ymixE[3][WMk];   // for output row y = 2*gy   (even)
    __shared__ float ymixO[3][WMk];   // for output row y = 2*gy+1 (odd)

    int tx = threadIdx.x;      // 0..255 = output x
    int gy = blockIdx.x;       // 0..127 -> rows 2gy, 2gy+1
    int z  = blockIdx.y;       // 0..47
    int ph = blockIdx.z;       // 0..3

    // even row taps: .25*row[gy-1] + .75*row[gy]
    // odd  row taps: .75*row[gy]   + .25*row[gy+1]   (clamped at edges)
    int gym1 = (gy > 0) ? gy - 1 : 0;
    int gyp1 = (gy < HMk - 1) ? gy + 1 : HMk - 1;

    const float* mbase = mvf + (size_t)ph * 3 * MVF_CH + (size_t)z * HMk * WMk;
    if (tx < WMk) {
#pragma unroll
        for (int c = 0; c < 3; c++) {
            const float* ch = mbase + (size_t)c * MVF_CH;
            float a = __ldg(ch + gym1 * WMk + tx);
            float m = __ldg(ch + gy   * WMk + tx);
            float b = __ldg(ch + gyp1 * WMk + tx);
            ymixE[c][tx] = fmaf(0.25f, a, 0.75f * m);
            ymixO[c][tx] = fmaf(0.75f, m, 0.25f * b);
        }
    }
    __syncthreads();

    // x-dim resize taps for output x = tx
    int  k    = tx >> 1;
    bool xodd = (tx & 1) != 0;
    int  xa   = xodd ? k : (k > 0 ? k - 1 : 0);
    int  xb   = xodd ? (k < WMk - 1 ? k + 1 : WMk - 1) : k;
    float wxa = xodd ? 0.75f : 0.25f;
    float wxb = 1.f - wxa;

    float ve[3], vo[3];
#pragma unroll
    for (int c = 0; c < 3; c++) {
        ve[c] = fmaf(wxa, ymixE[c][xa], wxb * ymixE[c][xb]);
        vo[c] = fmaf(wxa, ymixO[c][xa], wxb * ymixO[c][xb]);
    }

    int ye = 2 * gy, yo = 2 * gy + 1;
    // flow scale (1, 2, 2); coords are absolute voxel coordinates
    float cze = (float)z + ve[0], cye = (float)ye + 2.f * ve[1],
          cxe = (float)tx + 2.f * ve[2];
    float czo = (float)z + vo[0], cyo = (float)yo + 2.f * vo[1],
          cxo = (float)tx + 2.f * vo[2];

    float2 re, ro;
    bool both = is_interior(cze, cye, cxe) & is_interior(czo, cyo, cxo);
    if (__all_sync(0xffffffffu, both)) {
        const uint2 *qe, *qo; __half2 wze, wye, wxe, wzo, wyo, wxo;
        fast_addrs(cze, cye, cxe, qe, wze, wye, wxe);
        fast_addrs(czo, cyo, cxo, qo, wzo, wyo, wxo);
        // 8 independent loads in flight before any math
        uint2 e00 = __ldg(qe);
        uint2 e01 = __ldg(qe + Ww);
        uint2 e10 = __ldg(qe + Hh * Ww);
        uint2 e11 = __ldg(qe + Hh * Ww + Ww);
        uint2 o00 = __ldg(qo);
        uint2 o01 = __ldg(qo + Ww);
        uint2 o10 = __ldg(qo + Hh * Ww);
        uint2 o11 = __ldg(qo + Hh * Ww + Ww);
        re = fast_lerp(e00, e01, e10, e11, wze, wye, wxe);
        ro = fast_lerp(o00, o01, o10, o11, wzo, wyo, wxo);
    } else {
        re = sample3d_h(cze, cye, cxe);
        ro = sample3d_h(czo, cyo, cxo);
    }

    float2* o2 = (float2*)(out + (size_t)(1 + ph) * CS);
    o2[(z * Hh + ye) * Ww + tx] = re;
    o2[(z * Hh + yo) * Ww + tx] = ro;
}

// ---------------------------------------------------------------------------
extern "C" void kernel_launch(void* const* d_in, const int* in_sizes, int n_in,
                              void* d_out, int out_size) {
    const float* image = (const float*)d_in[0];   // (1,1,48,256,256,2) f32
    const float* mvf   = (const float*)d_in[1];   // (1,4,3,48,128,128) f32
    float* out = (float*)d_out;                   // (1,5,48,256,256,2) f32

    prep_kernel<<<(NPIX + 255) / 256, 256>>>((const float2*)image,
                                             (float2*)out);

    dim3 grid(Hh / 2, Dd, PHn);
    warp_kernel<<<grid, 256>>>(mvf, out);
}